// round 16
// baseline (speedup 1.0000x reference)
#include <cuda_runtime.h>
#include <mma.h>
#include <cuda_fp16.h>
#include <cstdint>

using namespace nvcuda;

#define N_IMG 48
#define Hc 128
#define Wc 128

__device__ __half g_y1[48u * 128u * 128u * 128u];  // conv1 POST-act fp16, NHWC
__device__ __half g_y2h[48u * 128u * 128u * 32u];  // conv2 POST-act fp16, NHWC
__device__ __half g_xr[48u * 128u * 128u * 64u];   // x fp16, NHWC
__device__ __half g_w1t[36 * 128 * 16];            // W1 fp16 [c][m][16]
__device__ __half g_w2t[8 * 9 * 32 * 16];          // W2 fp16 [cc][tap][m][16]
__device__ __half g_wu[9 * 16 * 32];               // Weff fp16 [tap][m(16)][ic]

__device__ __forceinline__ uint32_t smem_u32(const void* p) {
    uint32_t a;
    asm("{ .reg .u64 t; cvta.to.shared.u64 t, %1; cvt.u32.u64 %0, t; }"
        : "=r"(a) : "l"(p));
    return a;
}
__device__ __forceinline__ void cpa16(uint32_t dst, const void* src, bool ok) {
    int sz = ok ? 16 : 0;
    asm volatile("cp.async.cg.shared.global [%0], [%1], 16, %2;"
                 :: "r"(dst), "l"(src), "r"(sz) : "memory");
}
__device__ __forceinline__ void cpa_commit() {
    asm volatile("cp.async.commit_group;" ::: "memory");
}
__device__ __forceinline__ void cpa_wait0() {
    asm volatile("cp.async.wait_group 0;" ::: "memory");
}
__device__ __forceinline__ void cpa_wait1() {
    asm volatile("cp.async.wait_group 1;" ::: "memory");
}

// ---- prep: x NCHW fp32 -> g_xr NHWC fp16 ----------------------------------
__global__ __launch_bounds__(256) void xt_k(const float* __restrict__ x) {
    __shared__ float t[64][129];
    const int y = blockIdx.x, img = blockIdx.y;
    for (int e = threadIdx.x; e < 64 * 128; e += 256) {
        int ic = e >> 7, px = e & 127;
        t[ic][px] = x[((size_t)(img * 64 + ic) * Hc + y) * Wc + px];
    }
    __syncthreads();
    __half* dst = &g_xr[(size_t)(img * Hc + y) * Wc * 64];
    for (int e = threadIdx.x; e < 1024; e += 256) {
        int px = e >> 3, j = (e & 7) << 3;
        __half h[8];
#pragma unroll
        for (int q = 0; q < 8; q++) h[q] = __float2half_rn(t[j + q][px]);
        *(uint4*)&dst[px * 64 + j] = *(uint4*)h;
    }
}

// ---- merged weight prep: wt1 + wt2 + wu -----------------------------------
__global__ __launch_bounds__(256) void wprep_k(
    const float* __restrict__ w1, const float* __restrict__ w2,
    const float* __restrict__ w3)
{
    int idx = blockIdx.x * 256 + threadIdx.x;
    if (idx < 73728) {                                 // W1: 36*128*16
        int kl = idx & 15, m = (idx >> 4) & 127, c = idx >> 11;
        int k = c * 16 + kl;
        int tap = k >> 6, ic = k & 63;
        g_w1t[idx] = __float2half_rn(w1[(m * 64 + ic) * 9 + tap]);
    } else if (idx < 73728 + 36864) {                  // W2: 8*9*32*16
        int i2 = idx - 73728;
        int j = i2 & 15, m = (i2 >> 4) & 31;
        int u = i2 >> 9, tap = u % 9, cc = u / 9;
        int ic = cc * 16 + j;
        g_w2t[i2] = __float2half_rn(w2[(m * 128 + ic) * 9 + tap]);
    } else if (idx < 73728 + 36864 + 4608) {           // Weff: 9*16*32
        int i3 = idx - 73728 - 36864;
        int ic = i3 & 31, m = (i3 >> 5) & 15, tap = i3 >> 9;
        float val = 0.f;
        if (m < 4) {
            const float CY[2][3][3] = {
                { {0.75f, 0.25f, 0.f}, {0.25f, 0.75f, 0.f}, {0.f, 0.75f, 0.25f} },
                { {0.25f, 0.75f, 0.f}, {0.f, 0.75f, 0.25f}, {0.f, 0.25f, 0.75f} } };
            int a = m >> 1, b = m & 1;
            int r = tap / 3, s = tap % 3;
            for (int dy = 0; dy < 3; dy++)
                for (int dx = 0; dx < 3; dx++)
                    val += w3[ic * 9 + dy * 3 + dx] * CY[a][dy][r] * CY[b][dx][s];
        }
        g_wu[(tap * 16 + m) * 32 + ic] = __float2half_rn(val);
    }
}

// ---------------------------------------------------------------------------
// conv1: fp16 wmma m16n16k16, 3-stage cp.async pipeline, 128-thread CTAs
// (4 CTAs/SM). CTA: M=128(oc) x N=64 px; grid (2 xblocks, 128 rows, 48 img).
// Warps 4(m) x 1(n): warp 32m x 64n, 8 acc frags. K=576 in 36 chunks of 16
// (tap, 16ch). wait_group 1 keeps one staging group in flight over mma.
// ---------------------------------------------------------------------------
__global__ __launch_bounds__(128, 4) void conv1_wmma_k(
    const float* __restrict__ b1)
{
    __shared__ __align__(16) __half sA[3][128 * 24];   // [m][kl], ldm 24
    __shared__ __align__(16) __half sB[3][64 * 24];    // [n][kl], ldm 24

    const int tid = threadIdx.x;
    const int lane = tid & 31, wid = tid >> 5;
    const int xb = blockIdx.x, band = blockIdx.y, img = blockIdx.z;

    const uint32_t sAu[3] = { smem_u32(sA[0]), smem_u32(sA[1]), smem_u32(sA[2]) };
    const uint32_t sBu[3] = { smem_u32(sB[0]), smem_u32(sB[1]), smem_u32(sB[2]) };

    auto issue = [&](int c, int buf) {
        const int tap = c >> 2, ic0 = (c & 3) << 4;
        const int ky = tap / 3, kx = tap % 3;
        const int yy = band + ky - 1;
        const bool yok = (unsigned)yy < (unsigned)Hc;
        // A: 128 m x 16 kl halves = 256 x 16B, 2 per thread
        for (int e = tid; e < 256; e += 128) {
            int m = e >> 1, h = (e & 1) << 3;
            cpa16(sAu[buf] + ((m * 24 + h) << 1),
                  &g_w1t[(c * 128 + m) * 16 + h], true);
        }
        // B: 64 px x 16 ch halves = 128 x 16B, 1 per thread
        {
            int n = tid >> 1, h = (tid & 1) << 3;
            int xx = xb * 64 + n + kx - 1;
            bool ok = yok && (unsigned)xx < (unsigned)Wc;
            const __half* src = ok ?
                &g_xr[((size_t)(img * Hc + yy) * Wc + xx) * 64 + ic0 + h] : g_xr;
            cpa16(sBu[buf] + ((n * 24 + h) << 1), src, ok);
        }
        cpa_commit();
    };

    wmma::fragment<wmma::accumulator, 16, 16, 16, float> acc[2][4];
#pragma unroll
    for (int wm = 0; wm < 2; wm++)
#pragma unroll
        for (int wn = 0; wn < 4; wn++) wmma::fill_fragment(acc[wm][wn], 0.f);

    issue(0, 0);
    issue(1, 1);
    for (int c = 0; c < 36; ++c) {
        const int buf = c % 3;
        if (c + 1 < 36) cpa_wait1(); else cpa_wait0();
        __syncthreads();
        if (c + 2 < 36) issue(c + 2, (c + 2) % 3);

        wmma::fragment<wmma::matrix_a, 16, 16, 16, __half,
                       wmma::row_major> af[2];
        wmma::fragment<wmma::matrix_b, 16, 16, 16, __half,
                       wmma::col_major> bf[4];
#pragma unroll
        for (int wm = 0; wm < 2; wm++)
            wmma::load_matrix_sync(af[wm],
                                   &sA[buf][(wid * 32 + wm * 16) * 24], 24);
#pragma unroll
        for (int wn = 0; wn < 4; wn++)
            wmma::load_matrix_sync(bf[wn], &sB[buf][(wn * 16) * 24], 24);
#pragma unroll
        for (int wm = 0; wm < 2; wm++)
#pragma unroll
            for (int wn = 0; wn < 4; wn++)
                wmma::mma_sync(acc[wm][wn], af[wm], bf[wn], acc[wm][wn]);
    }

    // epilogue: bias+relu, NHWC fp16 16B stores (smem reused as fp32 scratch)
    __syncthreads();
    float* scr = reinterpret_cast<float*>(sA[0]) + wid * 272;
    const int px = lane >> 1, half = lane & 1;
#pragma unroll
    for (int wm = 0; wm < 2; wm++)
#pragma unroll
        for (int wn = 0; wn < 4; wn++) {
            wmma::store_matrix_sync(scr, acc[wm][wn], 16, wmma::mem_row_major);
            __syncwarp();
            int m0 = wid * 32 + wm * 16 + half * 8;
            int x = xb * 64 + wn * 16 + px;
            __half hv[8];
#pragma unroll
            for (int j = 0; j < 8; j++)
                hv[j] = __float2half_rn(
                    fmaxf(scr[(half * 8 + j) * 16 + px] + b1[m0 + j], 0.f));
            __half* dp = &g_y1[((size_t)(img * Hc + band) * Wc + x) * 128 + m0];
            *(uint4*)dp = *(uint4*)hv;
            __syncwarp();
        }
}

// ---------------------------------------------------------------------------
// conv2: unchanged (proven). fp16 wmma tap-reuse, epilogue -> fp16 NHWC.
// ---------------------------------------------------------------------------
__global__ __launch_bounds__(256, 2) void conv2_wmma_k(
    const float* __restrict__ b2)
{
    __shared__ __align__(16) __half sA[9 * 32 * 24];    // [tap][m][kl], ldm 24
    __shared__ __align__(16) __half sB[4 * 130 * 24];   // [row][px+1][ch], 24

    const int tid = threadIdx.x;
    const int lane = tid & 31, wid = tid >> 5;
    const int r = wid >> 2, x0 = (wid & 3) << 5;
    const int band = blockIdx.x, img = blockIdx.y;

    const uint32_t sAu = smem_u32(sA), sBu = smem_u32(sB);

    wmma::fragment<wmma::accumulator, 16, 16, 16, float> acc[2][2];
#pragma unroll
    for (int wm = 0; wm < 2; wm++)
#pragma unroll
        for (int wn = 0; wn < 2; wn++) wmma::fill_fragment(acc[wm][wn], 0.f);

    for (int cc = 0; cc < 8; ++cc) {
        __syncthreads();
        for (int e = tid; e < 576; e += 256) {
            int q = e >> 1, h = (e & 1) << 3;
            cpa16(sAu + ((q * 24 + h) << 1),
                  &g_w2t[((cc * 9) * 32 + q) * 16 + h], true);
        }
        for (int e = tid; e < 1040; e += 256) {
            int p = e >> 1, h = (e & 1) << 3;
            int row = p / 130, pxi = p % 130;
            int yy = band * 2 - 1 + row;
            int xx = pxi - 1;
            bool ok = (unsigned)yy < (unsigned)Hc && (unsigned)xx < (unsigned)Wc;
            const __half* src = ok ?
                &g_y1[((size_t)(img * Hc + yy) * Wc + xx) * 128 + cc * 16 + h]
                : g_y1;
            cpa16(sBu + ((p * 24 + h) << 1), src, ok);
        }
        cpa_commit();
        cpa_wait0();
        __syncthreads();

#pragma unroll
        for (int tap = 0; tap < 9; ++tap) {
            const int ky = tap / 3, kx = tap % 3;
            wmma::fragment<wmma::matrix_a, 16, 16, 16, __half,
                           wmma::row_major> af[2];
            wmma::fragment<wmma::matrix_b, 16, 16, 16, __half,
                           wmma::col_major> bf[2];
#pragma unroll
            for (int wm = 0; wm < 2; wm++)
                wmma::load_matrix_sync(af[wm],
                                       &sA[(tap * 32 + wm * 16) * 24], 24);
#pragma unroll
            for (int wn = 0; wn < 2; wn++)
                wmma::load_matrix_sync(
                    bf[wn],
                    &sB[((r + ky) * 130 + x0 + wn * 16 + kx) * 24], 24);
#pragma unroll
            for (int wm = 0; wm < 2; wm++)
#pragma unroll
                for (int wn = 0; wn < 2; wn++)
                    wmma::mma_sync(acc[wm][wn], af[wm], bf[wn], acc[wm][wn]);
        }
    }

    __syncthreads();
    float* scr = reinterpret_cast<float*>(sA) + wid * 272;
    const int px = lane >> 1, half = lane & 1;
    const int y = band * 2 + r;
#pragma unroll
    for (int wm = 0; wm < 2; wm++)
#pragma unroll
        for (int wn = 0; wn < 2; wn++) {
            wmma::store_matrix_sync(scr, acc[wm][wn], 16, wmma::mem_row_major);
            __syncwarp();
            int m0 = wm * 16 + half * 8;
            int x = x0 + wn * 16 + px;
            __half hv[8];
#pragma unroll
            for (int j = 0; j < 8; j++)
                hv[j] = __float2half_rn(
                    fmaxf(scr[(half * 8 + j) * 16 + px] + b2[m0 + j], 0.f));
            __half* dp = &g_y2h[((size_t)(img * Hc + y) * Wc + x) * 32 + m0];
            *(uint4*)dp = *(uint4*)hv;
            __syncwarp();
        }
}

// ---------------------------------------------------------------------------
// upconv as GEMM (unchanged): M=16 parities x N=128 v-px x K=288.
// ---------------------------------------------------------------------------
__global__ __launch_bounds__(256) void upconv_mma_k(
    const float* __restrict__ b3, float* __restrict__ out)
{
    __shared__ __align__(16) __half sA[9 * 16 * 40];
    __shared__ __align__(16) __half sB[3 * 130 * 40];

    const int tid = threadIdx.x;
    const int lane = tid & 31, wid = tid >> 5;
    const int i = blockIdx.x, img = blockIdx.y;
    const int j0 = wid << 4;

    const uint32_t sAu = smem_u32(sA), sBu = smem_u32(sB);

    for (int e = tid; e < 576; e += 256) {
        int q = e >> 2, h = (e & 3) << 3;
        cpa16(sAu + ((q * 40 + h) << 1), &g_wu[q * 32 + h], true);
    }
    for (int e = tid; e < 1560; e += 256) {
        int p = e >> 2, h = (e & 2 ? 16 : 0) + ((e & 1) << 3);
        int row = p / 130, pxi = p % 130;
        int vy = min(max(i - 1 + row, 0), Hc - 1);
        int vx = min(max(pxi - 1, 0), Wc - 1);
        cpa16(sBu + ((p * 40 + h) << 1),
              &g_y2h[((size_t)(img * Hc + vy) * Wc + vx) * 32 + h], true);
    }
    cpa_commit();
    cpa_wait0();
    __syncthreads();

    wmma::fragment<wmma::accumulator, 16, 16, 16, float> acc;
    wmma::fill_fragment(acc, 0.f);

#pragma unroll
    for (int tap = 0; tap < 9; ++tap) {
        const int r = tap / 3, s = tap % 3;
#pragma unroll
        for (int ks = 0; ks < 2; ++ks) {
            wmma::fragment<wmma::matrix_a, 16, 16, 16, __half,
                           wmma::row_major> af;
            wmma::fragment<wmma::matrix_b, 16, 16, 16, __half,
                           wmma::col_major> bf;
            wmma::load_matrix_sync(af, &sA[(tap * 16) * 40 + ks * 16], 40);
            wmma::load_matrix_sync(bf, &sB[(r * 130 + j0 + s) * 40 + ks * 16],
                                   40);
            wmma::mma_sync(acc, af, bf, acc);
        }
    }

    __syncthreads();
    float* scr = reinterpret_cast<float*>(sB) + wid * 272;
    wmma::store_matrix_sync(scr, acc, 16, wmma::mem_row_major);
    __syncwarp();
    const float bv = b3[0];
    float* op = &out[(size_t)img * 256 * 256];
#pragma unroll
    for (int e = lane; e < 64; e += 32) {
        int m = e >> 4, j = e & 15;
        int a = m >> 1, b = m & 1;
        op[(2 * i + a) * 256 + 2 * (j0 + j) + b] = scr[m * 16 + j] + bv;
    }
}

// ---------------------------------------------------------------------------
// Border fixup (unchanged): exact 1-px output frame.
// ---------------------------------------------------------------------------
__global__ __launch_bounds__(256) void border_k(
    const float* __restrict__ w3, const float* __restrict__ b3,
    float* __restrict__ out)
{
    const int img = blockIdx.x;
    const __half* v = &g_y2h[(size_t)img * Hc * Wc * 32];
    for (int pid = threadIdx.x; pid < 1020; pid += 256) {
        int ty, tx;
        if (pid < 256)      { ty = 0;            tx = pid; }
        else if (pid < 512) { ty = 255;          tx = pid - 256; }
        else if (pid < 766) { ty = pid - 512 + 1; tx = 0; }
        else                { ty = pid - 766 + 1; tx = 255; }

        float acc = 0.f;
        for (int dy = 0; dy < 3; dy++) {
            int t = ty + dy - 1;
            if ((unsigned)t >= 256u) continue;
            int p0, p1; float wy0, wy1;
            if (t & 1) { p0 = t >> 1; p1 = p0 + 1; wy0 = 0.75f; wy1 = 0.25f; }
            else       { p0 = (t >> 1) - 1; p1 = t >> 1; wy0 = 0.25f; wy1 = 0.75f; }
            p0 = min(max(p0, 0), Hc - 1); p1 = min(max(p1, 0), Hc - 1);
            for (int dx = 0; dx < 3; dx++) {
                int s = tx + dx - 1;
                if ((unsigned)s >= 256u) continue;
                int q0, q1; float wx0, wx1;
                if (s & 1) { q0 = s >> 1; q1 = q0 + 1; wx0 = 0.75f; wx1 = 0.25f; }
                else       { q0 = (s >> 1) - 1; q1 = s >> 1; wx0 = 0.25f; wx1 = 0.75f; }
                q0 = min(max(q0, 0), Wc - 1); q1 = min(max(q1, 0), Wc - 1);
                const __half* v00 = &v[(p0 * Wc + q0) * 32];
                const __half* v01 = &v[(p0 * Wc + q1) * 32];
                const __half* v10 = &v[(p1 * Wc + q0) * 32];
                const __half* v11 = &v[(p1 * Wc + q1) * 32];
                for (int ic = 0; ic < 32; ic++) {
                    float u = wy0 * (wx0 * __half2float(v00[ic]) +
                                     wx1 * __half2float(v01[ic])) +
                              wy1 * (wx0 * __half2float(v10[ic]) +
                                     wx1 * __half2float(v11[ic]));
                    acc += w3[ic * 9 + dy * 3 + dx] * u;
                }
            }
        }
        out[((size_t)img * 256 + ty) * 256 + tx] = acc + b3[0];
    }
}

// ---------------------------------------------------------------------------
extern "C" void kernel_launch(void* const* d_in, const int* in_sizes, int n_in,
                              void* d_out, int out_size)
{
    const float* x  = (const float*)d_in[0];
    const float* W1 = (const float*)d_in[3];
    const float* b1 = (const float*)d_in[4];
    const float* W2 = (const float*)d_in[5];
    const float* b2 = (const float*)d_in[6];
    const float* W3 = (const float*)d_in[7];
    const float* b3 = (const float*)d_in[8];
    float* out = (float*)d_out;

    xt_k<<<dim3(Hc, N_IMG), 256>>>(x);
    wprep_k<<<(73728 + 36864 + 4608 + 255) / 256, 256>>>(W1, W2, W3);

    conv1_wmma_k<<<dim3(2, Hc, N_IMG), 128>>>(b1);
    conv2_wmma_k<<<dim3(Hc / 2, N_IMG), 256>>>(b2);
    upconv_mma_k<<<dim3(Hc, N_IMG), 256>>>(b3, out);
    border_k<<<N_IMG, 256>>>(W3, b3, out);
}

// round 17
// speedup vs baseline: 1.0623x; 1.0623x over previous
#include <cuda_runtime.h>
#include <mma.h>
#include <cuda_fp16.h>
#include <cstdint>

using namespace nvcuda;

#define N_IMG 48
#define Hc 128
#define Wc 128

__device__ __half g_y1[48u * 128u * 128u * 128u];  // conv1 POST-act fp16, NHWC
__device__ __half g_y2h[48u * 128u * 128u * 32u];  // conv2 POST-act fp16, NHWC
__device__ __half g_xr[48u * 128u * 128u * 64u];   // x fp16, NHWC
__device__ __half g_w1t[36 * 128 * 16];            // W1 fp16 [c][m][16]
__device__ __half g_w2t[8 * 9 * 32 * 16];          // W2 fp16 [cc][tap][m][16]
__device__ __half g_wu[9 * 16 * 32];               // Weff fp16 [tap][m(16)][ic]

__device__ __forceinline__ uint32_t smem_u32(const void* p) {
    uint32_t a;
    asm("{ .reg .u64 t; cvta.to.shared.u64 t, %1; cvt.u32.u64 %0, t; }"
        : "=r"(a) : "l"(p));
    return a;
}
__device__ __forceinline__ void cpa16(uint32_t dst, const void* src, bool ok) {
    int sz = ok ? 16 : 0;
    asm volatile("cp.async.cg.shared.global [%0], [%1], 16, %2;"
                 :: "r"(dst), "l"(src), "r"(sz) : "memory");
}
__device__ __forceinline__ void cpa_commit() {
    asm volatile("cp.async.commit_group;" ::: "memory");
}
__device__ __forceinline__ void cpa_wait0() {
    asm volatile("cp.async.wait_group 0;" ::: "memory");
}

// ---- prep: x NCHW fp32 -> g_xr NHWC fp16 ----------------------------------
__global__ __launch_bounds__(256) void xt_k(const float* __restrict__ x) {
    __shared__ float t[64][129];
    const int y = blockIdx.x, img = blockIdx.y;
    for (int e = threadIdx.x; e < 64 * 128; e += 256) {
        int ic = e >> 7, px = e & 127;
        t[ic][px] = x[((size_t)(img * 64 + ic) * Hc + y) * Wc + px];
    }
    __syncthreads();
    __half* dst = &g_xr[(size_t)(img * Hc + y) * Wc * 64];
    for (int e = threadIdx.x; e < 1024; e += 256) {
        int px = e >> 3, j = (e & 7) << 3;
        __half h[8];
#pragma unroll
        for (int q = 0; q < 8; q++) h[q] = __float2half_rn(t[j + q][px]);
        *(uint4*)&dst[px * 64 + j] = *(uint4*)h;
    }
}

// ---- merged weight prep: wt1 + wt2 + wu -----------------------------------
__global__ __launch_bounds__(256) void wprep_k(
    const float* __restrict__ w1, const float* __restrict__ w2,
    const float* __restrict__ w3)
{
    int idx = blockIdx.x * 256 + threadIdx.x;
    if (idx < 73728) {                                 // W1: 36*128*16
        int kl = idx & 15, m = (idx >> 4) & 127, c = idx >> 11;
        int k = c * 16 + kl;
        int tap = k >> 6, ic = k & 63;
        g_w1t[idx] = __float2half_rn(w1[(m * 64 + ic) * 9 + tap]);
    } else if (idx < 73728 + 36864) {                  // W2: 8*9*32*16
        int i2 = idx - 73728;
        int j = i2 & 15, m = (i2 >> 4) & 31;
        int u = i2 >> 9, tap = u % 9, cc = u / 9;
        int ic = cc * 16 + j;
        g_w2t[i2] = __float2half_rn(w2[(m * 128 + ic) * 9 + tap]);
    } else if (idx < 73728 + 36864 + 4608) {           // Weff: 9*16*32
        int i3 = idx - 73728 - 36864;
        int ic = i3 & 31, m = (i3 >> 5) & 15, tap = i3 >> 9;
        float val = 0.f;
        if (m < 4) {
            const float CY[2][3][3] = {
                { {0.75f, 0.25f, 0.f}, {0.25f, 0.75f, 0.f}, {0.f, 0.75f, 0.25f} },
                { {0.25f, 0.75f, 0.f}, {0.f, 0.75f, 0.25f}, {0.f, 0.25f, 0.75f} } };
            int a = m >> 1, b = m & 1;
            int r = tap / 3, s = tap % 3;
            for (int dy = 0; dy < 3; dy++)
                for (int dx = 0; dx < 3; dx++)
                    val += w3[ic * 9 + dy * 3 + dx] * CY[a][dy][r] * CY[b][dx][s];
        }
        g_wu[(tap * 16 + m) * 32 + ic] = __float2half_rn(val);
    }
}

// ---------------------------------------------------------------------------
// conv1: R14/R15 shape (256 thr, M=128 x N=128 px, warps 4x2), K-chunk 32
// (two k16 taps per chunk): 18 chunks, half the barriers, 16 mma/warp per
// chunk. mma k-order identical to chunk-16 version -> bit-identical results.
// Strides 40 halves (80B): ldmatrix rows hit distinct banks.
// ---------------------------------------------------------------------------
__global__ __launch_bounds__(256, 2) void conv1_wmma_k(
    const float* __restrict__ b1)
{
    __shared__ __align__(16) __half sA[2][128 * 40];   // [m][kl(32)], ldm 40
    __shared__ __align__(16) __half sB[2][128 * 40];   // [n][kl(32)], ldm 40

    const int tid = threadIdx.x;
    const int lane = tid & 31, wid = tid >> 5;
    const int warpM = wid >> 1, warpN = wid & 1;
    const int band = blockIdx.x, img = blockIdx.y;

    const uint32_t sAu[2] = { smem_u32(sA[0]), smem_u32(sA[1]) };
    const uint32_t sBu[2] = { smem_u32(sB[0]), smem_u32(sB[1]) };

    // chunk c2 covers old k16-chunks (2*c2, 2*c2+1)
    auto issue = [&](int c2, int buf) {
#pragma unroll
        for (int s = 0; s < 2; ++s) {
            const int c = 2 * c2 + s;
            const int tap = c >> 2, ic0 = (c & 3) << 4;
            const int ky = tap / 3, kx = tap % 3;
            const int yy = band + ky - 1;
            const bool yok = (unsigned)yy < (unsigned)Hc;
            {   // A: 128 m x 16 kl halves = 256 x 16B
                int m = tid >> 1, h = (tid & 1) << 3;
                cpa16(sAu[buf] + ((m * 40 + s * 16 + h) << 1),
                      &g_w1t[(c * 128 + m) * 16 + h], true);
            }
            {   // B: 128 px x 16 ch halves = 256 x 16B
                int n = tid >> 1, h = (tid & 1) << 3;
                int xx = n + kx - 1;
                bool ok = yok && (unsigned)xx < (unsigned)Wc;
                const __half* src = ok ?
                    &g_xr[((size_t)(img * Hc + yy) * Wc + xx) * 64 + ic0 + h]
                    : g_xr;
                cpa16(sBu[buf] + ((n * 40 + s * 16 + h) << 1), src, ok);
            }
        }
        cpa_commit();
    };

    wmma::fragment<wmma::accumulator, 16, 16, 16, float> acc[2][4];
#pragma unroll
    for (int wm = 0; wm < 2; wm++)
#pragma unroll
        for (int wn = 0; wn < 4; wn++) wmma::fill_fragment(acc[wm][wn], 0.f);

    issue(0, 0);
    for (int c2 = 0; c2 < 18; ++c2) {
        const int buf = c2 & 1;
        cpa_wait0();
        __syncthreads();
        if (c2 + 1 < 18) issue(c2 + 1, (c2 + 1) & 1);

#pragma unroll
        for (int s = 0; s < 2; ++s) {
            wmma::fragment<wmma::matrix_a, 16, 16, 16, __half,
                           wmma::row_major> af[2];
            wmma::fragment<wmma::matrix_b, 16, 16, 16, __half,
                           wmma::col_major> bf[4];
#pragma unroll
            for (int wm = 0; wm < 2; wm++)
                wmma::load_matrix_sync(
                    af[wm], &sA[buf][(warpM * 32 + wm * 16) * 40 + s * 16], 40);
#pragma unroll
            for (int wn = 0; wn < 4; wn++)
                wmma::load_matrix_sync(
                    bf[wn], &sB[buf][(warpN * 64 + wn * 16) * 40 + s * 16], 40);
#pragma unroll
            for (int wm = 0; wm < 2; wm++)
#pragma unroll
                for (int wn = 0; wn < 4; wn++)
                    wmma::mma_sync(acc[wm][wn], af[wm], bf[wn], acc[wm][wn]);
        }
    }

    // epilogue: bias+relu, NHWC fp16 16B stores (smem reused as fp32 scratch)
    __syncthreads();
    float* scr = reinterpret_cast<float*>(sA[0]) + wid * 272;
    const int px = lane >> 1, half = lane & 1;
#pragma unroll
    for (int wm = 0; wm < 2; wm++)
#pragma unroll
        for (int wn = 0; wn < 4; wn++) {
            wmma::store_matrix_sync(scr, acc[wm][wn], 16, wmma::mem_row_major);
            __syncwarp();
            int m0 = warpM * 32 + wm * 16 + half * 8;
            int n0 = warpN * 64 + wn * 16;
            __half hv[8];
#pragma unroll
            for (int j = 0; j < 8; j++)
                hv[j] = __float2half_rn(
                    fmaxf(scr[(half * 8 + j) * 16 + px] + b1[m0 + j], 0.f));
            __half* dp = &g_y1[((size_t)(img * Hc + band) * Wc + n0 + px) * 128
                               + m0];
            *(uint4*)dp = *(uint4*)hv;
            __syncwarp();
        }
}

// ---------------------------------------------------------------------------
// conv2: unchanged (proven). fp16 wmma tap-reuse, epilogue -> fp16 NHWC.
// ---------------------------------------------------------------------------
__global__ __launch_bounds__(256, 2) void conv2_wmma_k(
    const float* __restrict__ b2)
{
    __shared__ __align__(16) __half sA[9 * 32 * 24];    // [tap][m][kl], ldm 24
    __shared__ __align__(16) __half sB[4 * 130 * 24];   // [row][px+1][ch], 24

    const int tid = threadIdx.x;
    const int lane = tid & 31, wid = tid >> 5;
    const int r = wid >> 2, x0 = (wid & 3) << 5;
    const int band = blockIdx.x, img = blockIdx.y;

    const uint32_t sAu = smem_u32(sA), sBu = smem_u32(sB);

    wmma::fragment<wmma::accumulator, 16, 16, 16, float> acc[2][2];
#pragma unroll
    for (int wm = 0; wm < 2; wm++)
#pragma unroll
        for (int wn = 0; wn < 2; wn++) wmma::fill_fragment(acc[wm][wn], 0.f);

    for (int cc = 0; cc < 8; ++cc) {
        __syncthreads();
        for (int e = tid; e < 576; e += 256) {
            int q = e >> 1, h = (e & 1) << 3;
            cpa16(sAu + ((q * 24 + h) << 1),
                  &g_w2t[((cc * 9) * 32 + q) * 16 + h], true);
        }
        for (int e = tid; e < 1040; e += 256) {
            int p = e >> 1, h = (e & 1) << 3;
            int row = p / 130, pxi = p % 130;
            int yy = band * 2 - 1 + row;
            int xx = pxi - 1;
            bool ok = (unsigned)yy < (unsigned)Hc && (unsigned)xx < (unsigned)Wc;
            const __half* src = ok ?
                &g_y1[((size_t)(img * Hc + yy) * Wc + xx) * 128 + cc * 16 + h]
                : g_y1;
            cpa16(sBu + ((p * 24 + h) << 1), src, ok);
        }
        cpa_commit();
        cpa_wait0();
        __syncthreads();

#pragma unroll
        for (int tap = 0; tap < 9; ++tap) {
            const int ky = tap / 3, kx = tap % 3;
            wmma::fragment<wmma::matrix_a, 16, 16, 16, __half,
                           wmma::row_major> af[2];
            wmma::fragment<wmma::matrix_b, 16, 16, 16, __half,
                           wmma::col_major> bf[2];
#pragma unroll
            for (int wm = 0; wm < 2; wm++)
                wmma::load_matrix_sync(af[wm],
                                       &sA[(tap * 32 + wm * 16) * 24], 24);
#pragma unroll
            for (int wn = 0; wn < 2; wn++)
                wmma::load_matrix_sync(
                    bf[wn],
                    &sB[((r + ky) * 130 + x0 + wn * 16 + kx) * 24], 24);
#pragma unroll
            for (int wm = 0; wm < 2; wm++)
#pragma unroll
                for (int wn = 0; wn < 2; wn++)
                    wmma::mma_sync(acc[wm][wn], af[wm], bf[wn], acc[wm][wn]);
        }
    }

    __syncthreads();
    float* scr = reinterpret_cast<float*>(sA) + wid * 272;
    const int px = lane >> 1, half = lane & 1;
    const int y = band * 2 + r;
#pragma unroll
    for (int wm = 0; wm < 2; wm++)
#pragma unroll
        for (int wn = 0; wn < 2; wn++) {
            wmma::store_matrix_sync(scr, acc[wm][wn], 16, wmma::mem_row_major);
            __syncwarp();
            int m0 = wm * 16 + half * 8;
            int x = x0 + wn * 16 + px;
            __half hv[8];
#pragma unroll
            for (int j = 0; j < 8; j++)
                hv[j] = __float2half_rn(
                    fmaxf(scr[(half * 8 + j) * 16 + px] + b2[m0 + j], 0.f));
            __half* dp = &g_y2h[((size_t)(img * Hc + y) * Wc + x) * 32 + m0];
            *(uint4*)dp = *(uint4*)hv;
            __syncwarp();
        }
}

// ---------------------------------------------------------------------------
// upconv as GEMM (unchanged): M=16 parities x N=128 v-px x K=288.
// ---------------------------------------------------------------------------
__global__ __launch_bounds__(256) void upconv_mma_k(
    const float* __restrict__ b3, float* __restrict__ out)
{
    __shared__ __align__(16) __half sA[9 * 16 * 40];
    __shared__ __align__(16) __half sB[3 * 130 * 40];

    const int tid = threadIdx.x;
    const int lane = tid & 31, wid = tid >> 5;
    const int i = blockIdx.x, img = blockIdx.y;
    const int j0 = wid << 4;

    const uint32_t sAu = smem_u32(sA), sBu = smem_u32(sB);

    for (int e = tid; e < 576; e += 256) {
        int q = e >> 2, h = (e & 3) << 3;
        cpa16(sAu + ((q * 40 + h) << 1), &g_wu[q * 32 + h], true);
    }
    for (int e = tid; e < 1560; e += 256) {
        int p = e >> 2, h = (e & 2 ? 16 : 0) + ((e & 1) << 3);
        int row = p / 130, pxi = p % 130;
        int vy = min(max(i - 1 + row, 0), Hc - 1);
        int vx = min(max(pxi - 1, 0), Wc - 1);
        cpa16(sBu + ((p * 40 + h) << 1),
              &g_y2h[((size_t)(img * Hc + vy) * Wc + vx) * 32 + h], true);
    }
    cpa_commit();
    cpa_wait0();
    __syncthreads();

    wmma::fragment<wmma::accumulator, 16, 16, 16, float> acc;
    wmma::fill_fragment(acc, 0.f);

#pragma unroll
    for (int tap = 0; tap < 9; ++tap) {
        const int r = tap / 3, s = tap % 3;
#pragma unroll
        for (int ks = 0; ks < 2; ++ks) {
            wmma::fragment<wmma::matrix_a, 16, 16, 16, __half,
                           wmma::row_major> af;
            wmma::fragment<wmma::matrix_b, 16, 16, 16, __half,
                           wmma::col_major> bf;
            wmma::load_matrix_sync(af, &sA[(tap * 16) * 40 + ks * 16], 40);
            wmma::load_matrix_sync(bf, &sB[(r * 130 + j0 + s) * 40 + ks * 16],
                                   40);
            wmma::mma_sync(acc, af, bf, acc);
        }
    }

    __syncthreads();
    float* scr = reinterpret_cast<float*>(sB) + wid * 272;
    wmma::store_matrix_sync(scr, acc, 16, wmma::mem_row_major);
    __syncwarp();
    const float bv = b3[0];
    float* op = &out[(size_t)img * 256 * 256];
#pragma unroll
    for (int e = lane; e < 64; e += 32) {
        int m = e >> 4, j = e & 15;
        int a = m >> 1, b = m & 1;
        op[(2 * i + a) * 256 + 2 * (j0 + j) + b] = scr[m * 16 + j] + bv;
    }
}

// ---------------------------------------------------------------------------
// Border fixup (unchanged): exact 1-px output frame.
// ---------------------------------------------------------------------------
__global__ __launch_bounds__(256) void border_k(
    const float* __restrict__ w3, const float* __restrict__ b3,
    float* __restrict__ out)
{
    const int img = blockIdx.x;
    const __half* v = &g_y2h[(size_t)img * Hc * Wc * 32];
    for (int pid = threadIdx.x; pid < 1020; pid += 256) {
        int ty, tx;
        if (pid < 256)      { ty = 0;            tx = pid; }
        else if (pid < 512) { ty = 255;          tx = pid - 256; }
        else if (pid < 766) { ty = pid - 512 + 1; tx = 0; }
        else                { ty = pid - 766 + 1; tx = 255; }

        float acc = 0.f;
        for (int dy = 0; dy < 3; dy++) {
            int t = ty + dy - 1;
            if ((unsigned)t >= 256u) continue;
            int p0, p1; float wy0, wy1;
            if (t & 1) { p0 = t >> 1; p1 = p0 + 1; wy0 = 0.75f; wy1 = 0.25f; }
            else       { p0 = (t >> 1) - 1; p1 = t >> 1; wy0 = 0.25f; wy1 = 0.75f; }
            p0 = min(max(p0, 0), Hc - 1); p1 = min(max(p1, 0), Hc - 1);
            for (int dx = 0; dx < 3; dx++) {
                int s = tx + dx - 1;
                if ((unsigned)s >= 256u) continue;
                int q0, q1; float wx0, wx1;
                if (s & 1) { q0 = s >> 1; q1 = q0 + 1; wx0 = 0.75f; wx1 = 0.25f; }
                else       { q0 = (s >> 1) - 1; q1 = s >> 1; wx0 = 0.25f; wx1 = 0.75f; }
                q0 = min(max(q0, 0), Wc - 1); q1 = min(max(q1, 0), Wc - 1);
                const __half* v00 = &v[(p0 * Wc + q0) * 32];
                const __half* v01 = &v[(p0 * Wc + q1) * 32];
                const __half* v10 = &v[(p1 * Wc + q0) * 32];
                const __half* v11 = &v[(p1 * Wc + q1) * 32];
                for (int ic = 0; ic < 32; ic++) {
                    float u = wy0 * (wx0 * __half2float(v00[ic]) +
                                     wx1 * __half2float(v01[ic])) +
                              wy1 * (wx0 * __half2float(v10[ic]) +
                                     wx1 * __half2float(v11[ic]));
                    acc += w3[ic * 9 + dy * 3 + dx] * u;
                }
            }
        }
        out[((size_t)img * 256 + ty) * 256 + tx] = acc + b3[0];
    }
}

// ---------------------------------------------------------------------------
extern "C" void kernel_launch(void* const* d_in, const int* in_sizes, int n_in,
                              void* d_out, int out_size)
{
    const float* x  = (const float*)d_in[0];
    const float* W1 = (const float*)d_in[3];
    const float* b1 = (const float*)d_in[4];
    const float* W2 = (const float*)d_in[5];
    const float* b2 = (const float*)d_in[6];
    const float* W3 = (const float*)d_in[7];
    const float* b3 = (const float*)d_in[8];
    float* out = (float*)d_out;

    xt_k<<<dim3(Hc, N_IMG), 256>>>(x);
    wprep_k<<<(73728 + 36864 + 4608 + 255) / 256, 256>>>(W1, W2, W3);

    conv1_wmma_k<<<dim3(Hc, N_IMG), 256>>>(b1);
    conv2_wmma_k<<<dim3(Hc / 2, N_IMG), 256>>>(b2);
    upconv_mma_k<<<dim3(Hc, N_IMG), 256>>>(b3, out);
    border_k<<<N_IMG, 256>>>(W3, b3, out);
}